// round 3
// baseline (speedup 1.0000x reference)
#include <cuda_runtime.h>
#include <cstddef>

// Shapes (fixed by the problem)
#define B 16
#define W 256
#define S 512
#define H 768
#define L 12
#define E 256

// hidden_states: [L, B, S, H] fp32, layer stride = B*S*H
#define LAYER_STRIDE ((size_t)B * S * H)

#define NBLOCKS (148 * 7)   // persistent: 7 blocks per SM, one wave

// Persistent kernel: each block loops over words bw = blockIdx.x + k*gridDim.x.
// Per word (256 threads; output row is exactly 1024 floats = 256 x float4):
//   threads [0,64):    copy W_embed[word_indices[b,w]] (E=256 fp32)
//   threads [64,256):  192 threads x float4 = 768 fp32 bert span-mean
//
// Span length is 1 or 2. Always issue 24 independent loads per bert thread:
// 12 from row s0, 12 from row (s1-1). When len==1 the rows coincide (L1 hits,
// no extra DRAM traffic) and the second accumulator is weighted by 0.
__global__ __launch_bounds__(256, 7)
void bert_lexer_kernel(const int* __restrict__ word_indices,
                       const int* __restrict__ span_start,
                       const int* __restrict__ span_end,
                       const float* __restrict__ W_embed,
                       const float* __restrict__ hidden,
                       float* __restrict__ out)
{
    const int tid = threadIdx.x;

    for (int bw = blockIdx.x; bw < B * W; bw += NBLOCKS) {
        const int b = bw >> 8;                 // W = 256
        float* orow = out + (size_t)bw * (E + H);

        if (tid < 64) {
            // ---- word embedding gather: 64 threads x float4 = 256 floats ----
            const int wi = word_indices[bw];
            const float4* src =
                reinterpret_cast<const float4*>(W_embed + (size_t)wi * E);
            float4 v = src[tid];
            __stcs(reinterpret_cast<float4*>(orow) + tid, v);
        } else {
            // ---- bert span mean: 192 threads x float4 = 768 floats ----
            const int t   = tid - 64;          // 0 .. 191
            const int s0  = span_start[bw];
            const int se  = span_end[bw];
            const int sl  = se - 1;            // last position (== s0 if len==1)
            const int len = se - s0;           // 1 or 2

            const float* p0 =
                hidden + ((size_t)b * S + (size_t)s0) * H + (size_t)t * 4;
            const float* p1 =
                hidden + ((size_t)b * S + (size_t)sl) * H + (size_t)t * 4;

            float4 a0 = make_float4(0.f, 0.f, 0.f, 0.f);
            float4 a1 = make_float4(0.f, 0.f, 0.f, 0.f);

            #pragma unroll
            for (int l = 0; l < L; ++l) {
                float4 v0 = *reinterpret_cast<const float4*>(
                    p0 + (size_t)l * LAYER_STRIDE);
                float4 v1 = *reinterpret_cast<const float4*>(
                    p1 + (size_t)l * LAYER_STRIDE);
                a0.x += v0.x; a0.y += v0.y; a0.z += v0.z; a0.w += v0.w;
                a1.x += v1.x; a1.y += v1.y; a1.z += v1.z; a1.w += v1.w;
            }

            const float w1  = (len > 1) ? 1.0f : 0.0f;
            const float inv = 1.0f / (12.0f * (float)len);

            float4 r;
            r.x = (a0.x + w1 * a1.x) * inv;
            r.y = (a0.y + w1 * a1.y) * inv;
            r.z = (a0.z + w1 * a1.z) * inv;
            r.w = (a0.w + w1 * a1.w) * inv;

            __stcs(reinterpret_cast<float4*>(orow + E) + t, r);
        }
    }
}

extern "C" void kernel_launch(void* const* d_in, const int* in_sizes, int n_in,
                              void* d_out, int out_size)
{
    const int*   word_indices = (const int*)  d_in[0];   // [B, W]
    const int*   span_start   = (const int*)  d_in[1];   // [B, W]
    const int*   span_end     = (const int*)  d_in[2];   // [B, W]
    const float* W_embed      = (const float*)d_in[3];   // [V, E]
    const float* hidden       = (const float*)d_in[4];   // [L, B, S, H]
    float*       out          = (float*)      d_out;     // [B, W, E+H]

    (void)in_sizes; (void)n_in; (void)out_size;

    bert_lexer_kernel<<<NBLOCKS, 256>>>(word_indices, span_start, span_end,
                                        W_embed, hidden, out);
}

// round 4
// speedup vs baseline: 1.0066x; 1.0066x over previous
#include <cuda_runtime.h>
#include <cstddef>

// Shapes (fixed by the problem)
#define B 16
#define W 256
#define S 512
#define H 768
#define L 12
#define E 256

// hidden_states: [L, B, S, H] fp32, layer stride = B*S*H
#define LAYER_STRIDE ((size_t)B * S * H)

// Block = 192 threads (6 warps) per (b, w) word. ALL threads do the bert
// span-mean (192 x float4 = 768 floats); threads [0,64) additionally issue
// the word-embedding gather (64 x float4 = 256 floats). Every warp carries
// 24-25 independent in-flight LDG.128 -> uniform outstanding-load depth.
//
// Span length is 1 or 2. Always issue 24 independent hidden loads per thread:
// 12 from row s0, 12 from row (s1-1). When len==1 the rows coincide (cache
// hits, no extra DRAM traffic) and the second accumulator is weighted by 0.
__global__ __launch_bounds__(192)
void bert_lexer_kernel(const int* __restrict__ word_indices,
                       const int* __restrict__ span_start,
                       const int* __restrict__ span_end,
                       const float* __restrict__ W_embed,
                       const float* __restrict__ hidden,
                       float* __restrict__ out)
{
    const int bw  = blockIdx.x;            // 0 .. B*W-1
    const int b   = bw >> 8;               // W = 256
    const int tid = threadIdx.x;           // 0 .. 191

    float* orow = out + (size_t)bw * (E + H);

    // ---- word embedding gather (threads 0..63), issued FIRST so it
    //      overlaps the bert loads ----
    float4 ev;
    if (tid < 64) {
        const int wi = word_indices[bw];
        ev = __ldcs(reinterpret_cast<const float4*>(W_embed + (size_t)wi * E) + tid);
    }

    // ---- bert span mean: 192 threads x float4 = 768 floats ----
    const int s0  = span_start[bw];
    const int se  = span_end[bw];
    const int sl  = se - 1;                // last position (== s0 if len==1)
    const int len = se - s0;               // 1 or 2

    const float* p0 = hidden + ((size_t)b * S + (size_t)s0) * H + (size_t)tid * 4;
    const float* p1 = hidden + ((size_t)b * S + (size_t)sl) * H + (size_t)tid * 4;

    float4 a0 = make_float4(0.f, 0.f, 0.f, 0.f);
    float4 a1 = make_float4(0.f, 0.f, 0.f, 0.f);

    #pragma unroll
    for (int l = 0; l < L; ++l) {
        float4 v0 = __ldcs(reinterpret_cast<const float4*>(p0 + (size_t)l * LAYER_STRIDE));
        float4 v1 = __ldcs(reinterpret_cast<const float4*>(p1 + (size_t)l * LAYER_STRIDE));
        a0.x += v0.x; a0.y += v0.y; a0.z += v0.z; a0.w += v0.w;
        a1.x += v1.x; a1.y += v1.y; a1.z += v1.z; a1.w += v1.w;
    }

    const float w1  = (len > 1) ? 1.0f : 0.0f;   // drop duplicate row if len==1
    const float inv = 1.0f / (12.0f * (float)len);

    float4 r;
    r.x = (a0.x + w1 * a1.x) * inv;
    r.y = (a0.y + w1 * a1.y) * inv;
    r.z = (a0.z + w1 * a1.z) * inv;
    r.w = (a0.w + w1 * a1.w) * inv;

    __stcs(reinterpret_cast<float4*>(orow + E) + tid, r);

    if (tid < 64) {
        __stcs(reinterpret_cast<float4*>(orow) + tid, ev);
    }
}

extern "C" void kernel_launch(void* const* d_in, const int* in_sizes, int n_in,
                              void* d_out, int out_size)
{
    const int*   word_indices = (const int*)  d_in[0];   // [B, W]
    const int*   span_start   = (const int*)  d_in[1];   // [B, W]
    const int*   span_end     = (const int*)  d_in[2];   // [B, W]
    const float* W_embed      = (const float*)d_in[3];   // [V, E]
    const float* hidden       = (const float*)d_in[4];   // [L, B, S, H]
    float*       out          = (float*)      d_out;     // [B, W, E+H]

    (void)in_sizes; (void)n_in; (void)out_size;

    bert_lexer_kernel<<<B * W, 192>>>(word_indices, span_start, span_end,
                                      W_embed, hidden, out);
}

// round 5
// speedup vs baseline: 1.0163x; 1.0097x over previous
#include <cuda_runtime.h>
#include <cstdint>
#include <cstddef>

// Shapes (fixed by the problem)
#define B 16
#define W 256
#define S 512
#define H 768
#define L 12
#define E 256

#define LAYER_STRIDE ((size_t)B * S * H)   // elements between layers
#define ROW_BYTES (H * 4)                  // 3072 bytes per (l,b,s) row
#define MAX_SLOTS (2 * L)                  // up to 24 staged rows
#define SMEM_ROWS_BYTES (MAX_SLOTS * ROW_BYTES)   // 73728
#define SMEM_TOTAL (SMEM_ROWS_BYTES + 16)         // + mbarrier

__device__ __forceinline__ uint32_t smem_u32(const void* p) {
    return (uint32_t)__cvta_generic_to_shared(p);
}

// One block per (b,w) word, 192 threads.
// Thread 0 bulk-copies the word's 12*len hidden rows into SMEM via
// cp.async.bulk (mbarrier transaction-byte completion -> in-flight bytes
// bounded by SMEM, not the L1tex wavefront queue). Threads [0,64) overlap
// the word-embedding gather. After the mbarrier flips, all 192 threads
// reduce their float4 column across the staged rows.
__global__ __launch_bounds__(192)
void bert_lexer_kernel(const int* __restrict__ word_indices,
                       const int* __restrict__ span_start,
                       const int* __restrict__ span_end,
                       const float* __restrict__ W_embed,
                       const float* __restrict__ hidden,
                       float* __restrict__ out)
{
    extern __shared__ __align__(16) char smem[];
    uint64_t* mbar = reinterpret_cast<uint64_t*>(smem + SMEM_ROWS_BYTES);
    const uint32_t mbar_addr = smem_u32(mbar);

    const int bw  = blockIdx.x;            // 0 .. B*W-1
    const int b   = bw >> 8;               // W = 256
    const int tid = threadIdx.x;           // 0 .. 191

    const int s0  = span_start[bw];
    const int len = span_end[bw] - s0;     // 1 or 2

    if (tid == 0) {
        asm volatile("mbarrier.init.shared.b64 [%0], 1;" :: "r"(mbar_addr) : "memory");
        asm volatile("fence.proxy.async.shared::cta;" ::: "memory");
    }
    __syncthreads();

    if (tid == 0) {
        const uint32_t nbytes = (uint32_t)(L * len) * ROW_BYTES;
        asm volatile("mbarrier.arrive.expect_tx.shared.b64 _, [%0], %1;"
                     :: "r"(mbar_addr), "r"(nbytes) : "memory");
        const float* row0 = hidden + ((size_t)b * S + (size_t)s0) * H;
        uint32_t dst = smem_u32(smem);
        const uint32_t rb = ROW_BYTES;
        #pragma unroll
        for (int l = 0; l < L; ++l) {
            const float* src = row0 + (size_t)l * LAYER_STRIDE;
            asm volatile(
                "cp.async.bulk.shared::cta.global.mbarrier::complete_tx::bytes "
                "[%0], [%1], %2, [%3];"
                :: "r"(dst), "l"(src), "r"(rb), "r"(mbar_addr) : "memory");
            dst += rb;
            if (len == 2) {
                asm volatile(
                    "cp.async.bulk.shared::cta.global.mbarrier::complete_tx::bytes "
                    "[%0], [%1], %2, [%3];"
                    :: "r"(dst), "l"(src + H), "r"(rb), "r"(mbar_addr) : "memory");
                dst += rb;
            }
        }
    }

    // ---- overlap: word embedding gather (threads 0..63) ----
    float* orow = out + (size_t)bw * (E + H);
    if (tid < 64) {
        const int wi = word_indices[bw];
        float4 ev = *(reinterpret_cast<const float4*>(W_embed + (size_t)wi * E) + tid);
        __stcs(reinterpret_cast<float4*>(orow) + tid, ev);
    }

    // ---- wait for all staged rows (acquire) ----
    {
        uint32_t done;
        asm volatile(
            "{\n\t.reg .pred p;\n\t"
            "mbarrier.try_wait.parity.acquire.cta.shared::cta.b64 p, [%1], %2, 0x989680;\n\t"
            "selp.b32 %0, 1, 0, p;\n\t}"
            : "=r"(done) : "r"(mbar_addr), "r"(0u) : "memory");
        if (!done) {
            asm volatile(
                "{\n\t.reg .pred P1;\n\t"
                "WAIT_LOOP:\n\t"
                "mbarrier.try_wait.parity.acquire.cta.shared::cta.b64 P1, [%0], %1, 0x989680;\n\t"
                "@P1 bra.uni WAIT_DONE;\n\t"
                "bra.uni WAIT_LOOP;\n\t"
                "WAIT_DONE:\n\t}"
                :: "r"(mbar_addr), "r"(0u) : "memory");
        }
    }

    // ---- reduce: each thread sums its float4 across 12*len staged rows ----
    const int nslots = L * len;            // 12 or 24
    const float4* sp = reinterpret_cast<const float4*>(smem) + tid;
    float4 acc = make_float4(0.f, 0.f, 0.f, 0.f);
    #pragma unroll 6
    for (int i = 0; i < nslots; ++i) {
        float4 v = sp[(size_t)i * (ROW_BYTES / 16)];
        acc.x += v.x; acc.y += v.y; acc.z += v.z; acc.w += v.w;
    }

    const float inv = 1.0f / (12.0f * (float)len);
    float4 r;
    r.x = acc.x * inv; r.y = acc.y * inv; r.z = acc.z * inv; r.w = acc.w * inv;
    __stcs(reinterpret_cast<float4*>(orow + E) + tid, r);
}

extern "C" void kernel_launch(void* const* d_in, const int* in_sizes, int n_in,
                              void* d_out, int out_size)
{
    const int*   word_indices = (const int*)  d_in[0];   // [B, W]
    const int*   span_start   = (const int*)  d_in[1];   // [B, W]
    const int*   span_end     = (const int*)  d_in[2];   // [B, W]
    const float* W_embed      = (const float*)d_in[3];   // [V, E]
    const float* hidden       = (const float*)d_in[4];   // [L, B, S, H]
    float*       out          = (float*)      d_out;     // [B, W, E+H]

    (void)in_sizes; (void)n_in; (void)out_size;

    cudaFuncSetAttribute(bert_lexer_kernel,
                         cudaFuncAttributeMaxDynamicSharedMemorySize, SMEM_TOTAL);

    bert_lexer_kernel<<<B * W, 192, SMEM_TOTAL>>>(word_indices, span_start,
                                                  span_end, W_embed, hidden, out);
}